// round 9
// baseline (speedup 1.0000x reference)
#include <cuda_runtime.h>
#include <cuda_bf16.h>
#include <cstdint>

// Problem constants
#define BB 8
#define QQ 128
#define KK 512
#define DD 256
#define UU 256
#define TQ 8               // q rows per score block
#define KC 32              // k rows per score block
#define TQO 4              // q rows per softout block

// Scratch (static device arrays: no allocation)
__device__ float g_qp[BB * QQ * UU];   // 1 MB
__device__ float g_kp[BB * KK * UU];   // 4 MB
__device__ float g_sc[BB * QQ * KK];   // 2 MB raw scores

__device__ __forceinline__ float tanh_approx(float x) {
    float y;
    asm("tanh.approx.f32 %0, %1;" : "=f"(y) : "f"(x));
    return y;
}

__device__ __forceinline__ void cp_async16(uint32_t smem, const void* g) {
    asm volatile("cp.async.cg.shared.global [%0], [%1], 16;\n" :: "r"(smem), "l"(g));
}
__device__ __forceinline__ void cp_commit() { asm volatile("cp.async.commit_group;\n"); }
template <int N>
__device__ __forceinline__ void cp_wait() { asm volatile("cp.async.wait_group %0;\n" :: "n"(N)); }

// ---------------------------------------------------------------------------
// Merged projection GEMM: rows [0,1024) = query@Wq -> g_qp,
//                         rows [1024,5120) = key@Wk -> g_kp.
// BM=64, BN=64, BK=16, 256 threads, 4x4 per-thread tile (high warp count
// for latency hiding), prefetched global loads.
// ---------------------------------------------------------------------------
__global__ __launch_bounds__(256) void proj_gemm(const float* __restrict__ query,
                                                 const float* __restrict__ key,
                                                 const float* __restrict__ Wq,
                                                 const float* __restrict__ Wk) {
    __shared__ float As[16][68];   // transposed A tile (68: 272B rows, 16B-aligned)
    __shared__ float Ws[16][64];

    const int tid = threadIdx.x;
    const int m0  = blockIdx.y * 64;
    const int n0  = blockIdx.x * 64;

    const float* A; const float* W; float* C;
    if (m0 < BB * QQ) { A = query + (size_t)m0 * DD;             W = Wq; C = g_qp + (size_t)m0 * UU; }
    else              { A = key   + (size_t)(m0 - BB * QQ) * DD; W = Wk; C = g_kp + (size_t)(m0 - BB * QQ) * UU; }

    const int ty = tid >> 4;            // 0..15 -> 4 output rows each
    const int tx = tid & 15;            // 0..15 -> 4 output cols each
    const int ar0 = tid >> 2;           // 0..63  A row
    const int ac  = (tid & 3) * 4;      // A col base within 16-k slab
    const int wr0 = tid >> 4;           // 0..15  W row
    const int wc  = (tid & 15) * 4;     // W col base

    float acc[4][4];
#pragma unroll
    for (int i = 0; i < 4; i++)
#pragma unroll
        for (int j = 0; j < 4; j++) acc[i][j] = 0.0f;

    // preload slab 0
    float4 a0 = *(const float4*)&A[ar0 * DD + ac];
    float4 w0 = *(const float4*)&W[wr0 * UU + n0 + wc];

    for (int k0 = 0; k0 < DD; k0 += 16) {
        __syncthreads();
        As[ac + 0][ar0] = a0.x; As[ac + 1][ar0] = a0.y;
        As[ac + 2][ar0] = a0.z; As[ac + 3][ar0] = a0.w;
        *(float4*)&Ws[wr0][wc] = w0;
        __syncthreads();
        if (k0 + 16 < DD) {   // prefetch next slab under compute
            a0 = *(const float4*)&A[ar0 * DD + k0 + 16 + ac];
            w0 = *(const float4*)&W[(k0 + 16 + wr0) * UU + n0 + wc];
        }
#pragma unroll
        for (int kk = 0; kk < 16; kk++) {
            float4 av = *(const float4*)&As[kk][ty * 4];
            float4 wv = *(const float4*)&Ws[kk][tx * 4];
            float am[4] = {av.x, av.y, av.z, av.w};
            float wn[4] = {wv.x, wv.y, wv.z, wv.w};
#pragma unroll
            for (int i = 0; i < 4; i++)
#pragma unroll
                for (int j = 0; j < 4; j++)
                    acc[i][j] = fmaf(am[i], wn[j], acc[i][j]);
        }
    }
#pragma unroll
    for (int i = 0; i < 4; i++) {
        float4 o = make_float4(acc[i][0], acc[i][1], acc[i][2], acc[i][3]);
        *(float4*)&C[(size_t)(ty * 4 + i) * UU + n0 + tx * 4] = o;
    }
}

// ---------------------------------------------------------------------------
// Score kernel: block per (chunk, qtile of 8, b). 256 thr, 8 warps.
// Warp w owns u4-range [8w, 8w+8); lane l = k-row. q/vw loads are
// warp-uniform broadcasts; k float4 loaded once per warp per u4.
// ---------------------------------------------------------------------------
__global__ __launch_bounds__(256, 4) void score_kernel(const int* __restrict__ valid_len,
                                                       const float* __restrict__ v_w) {
    __shared__ float4 kb[KC * 64];        // 32KB swizzled kp chunk
    __shared__ float  qp_s[TQ * UU];      // 8KB
    __shared__ float  vw_s[UU];           // 1KB
    __shared__ float  part[8][TQ][32];    // 8KB u-partials

    const int b  = blockIdx.z;
    const int vl = __ldg(&valid_len[b]);
    const int k0 = blockIdx.x * KC;
    if (k0 >= vl) return;

    const int tid = threadIdx.x;
    const int q0  = blockIdx.y * TQ;

    {
        const float4* qg = (const float4*)(g_qp + (size_t)(b * QQ + q0) * UU);
        ((float4*)qp_s)[tid]       = qg[tid];
        ((float4*)qp_s)[tid + 256] = qg[tid + 256];
        if (tid < 64) ((float4*)vw_s)[tid] = ((const float4*)v_w)[tid];
    }

    const float4* src = (const float4*)(g_kp + ((size_t)b * KK + k0) * UU);
    const uint32_t kb_base = (uint32_t)__cvta_generic_to_shared(kb);
#pragma unroll
    for (int i = 0; i < 8; i++) {
        int idx = tid + i * 256;
        int rr = idx >> 6, cc = idx & 63;
        cp_async16(kb_base + ((uint32_t)(rr * 64 + (cc ^ (rr & 7))) << 4), src + idx);
    }
    cp_commit();
    cp_wait<0>();
    __syncthreads();

    const int w = tid >> 5, l = tid & 31;
    const float4* kbuf = kb + l * 64;
    const float4* qp4  = (const float4*)qp_s;
    const float4* vw4  = (const float4*)vw_s;
    const int u0  = w * 8;
    const int swl = l & 7;

    float acc[TQ];
#pragma unroll
    for (int r = 0; r < TQ; r++) acc[r] = 0.0f;

#pragma unroll
    for (int j = 0; j < 8; j++) {
        const int u4 = u0 + j;
        float4 k4 = kbuf[u4 ^ swl];        // spread, conflict-free
        float4 vv = vw4[u4];               // uniform broadcast
#pragma unroll
        for (int r = 0; r < TQ; r++) {
            float4 q = qp4[r * 64 + u4];   // uniform broadcast
            acc[r] = fmaf(vv.x, tanh_approx(q.x + k4.x),
                     fmaf(vv.y, tanh_approx(q.y + k4.y),
                     fmaf(vv.z, tanh_approx(q.z + k4.z),
                     fmaf(vv.w, tanh_approx(q.w + k4.w), acc[r]))));
        }
    }
#pragma unroll
    for (int r = 0; r < TQ; r++) part[w][r][l] = acc[r];
    __syncthreads();

    {   // 256 threads = 8 rows x 32 lanes: reduce over 8 warps and store
        const int r = tid >> 5, ll = tid & 31;
        float s = 0.f;
#pragma unroll
        for (int ww = 0; ww < 8; ww++) s += part[ww][r][ll];
        g_sc[(size_t)(b * QQ + q0 + r) * KK + k0 + ll] = s;
    }
}

// ---------------------------------------------------------------------------
// Softmax + output, d-split: block = (qtile, b, d-half). 128 threads.
// ---------------------------------------------------------------------------
__global__ __launch_bounds__(128) void softout_kernel(const float* __restrict__ value,
                                                      const int* __restrict__ valid_len,
                                                      float* __restrict__ out) {
    __shared__ float sc[TQO * KK];         // 8KB normalized attn

    const int tid = threadIdx.x;
    const int b   = blockIdx.y;
    const int q0  = blockIdx.x * TQO;
    const int dh  = blockIdx.z * 128;
    const int vl  = __ldg(&valid_len[b]);
    const int w = tid >> 5, l = tid & 31;

    {   // warp w: softmax of row w
        const float* row = g_sc + (size_t)(b * QQ + q0 + w) * KK;
        float vals[16];
        float m = -3.0e38f;
#pragma unroll
        for (int i = 0; i < 16; i++) {
            int k = l + 32 * i;
            float s = (k < vl) ? __ldg(&row[k]) : -1e6f;
            vals[i] = s;
            m = fmaxf(m, s);
        }
#pragma unroll
        for (int off = 16; off; off >>= 1) m = fmaxf(m, __shfl_xor_sync(0xffffffffu, m, off));
        float ssum = 0.0f;
#pragma unroll
        for (int i = 0; i < 16; i++) {
            float e = __expf(vals[i] - m);
            vals[i] = e;
            ssum += e;
        }
#pragma unroll
        for (int off = 16; off; off >>= 1) ssum += __shfl_xor_sync(0xffffffffu, ssum, off);
        float inv = 1.0f / ssum;
#pragma unroll
        for (int i = 0; i < 16; i++) sc[w * KK + l + 32 * i] = vals[i] * inv;
    }
    __syncthreads();

    const int d = dh + tid;
    float oacc[TQO];
#pragma unroll
    for (int q = 0; q < TQO; q++) oacc[q] = 0.0f;
    const float* vb = value + (size_t)b * KK * DD;
    const int kend = (vl + 3) & ~3;
#pragma unroll 2
    for (int k = 0; k < kend; k += 4) {
        float v0 = vb[(k + 0) * DD + d];
        float v1 = vb[(k + 1) * DD + d];
        float v2 = vb[(k + 2) * DD + d];
        float v3 = vb[(k + 3) * DD + d];
#pragma unroll
        for (int q = 0; q < TQO; q++) {
            float4 a = *(const float4*)&sc[q * KK + k];
            oacc[q] = fmaf(a.x, v0, fmaf(a.y, v1, fmaf(a.z, v2, fmaf(a.w, v3, oacc[q]))));
        }
    }
    float* ob = out + (size_t)(b * QQ + q0) * DD + d;
#pragma unroll
    for (int q = 0; q < TQO; q++) ob[q * DD] = oacc[q];
}

// ---------------------------------------------------------------------------
// Launch
// ---------------------------------------------------------------------------
extern "C" void kernel_launch(void* const* d_in, const int* in_sizes, int n_in,
                              void* d_out, int out_size) {
    const float* query     = (const float*)d_in[0];
    const float* key       = (const float*)d_in[1];
    const float* value     = (const float*)d_in[2];
    const int*   valid_len = (const int*)d_in[3];
    const float* Wq        = (const float*)d_in[4];
    const float* Wk        = (const float*)d_in[5];
    const float* v_w       = (const float*)d_in[6];
    float* out = (float*)d_out;

    proj_gemm<<<dim3(UU / 64, (BB * QQ + BB * KK) / 64), 256>>>(query, key, Wq, Wk);
    score_kernel<<<dim3(KK / KC, QQ / TQ, BB), 256>>>(valid_len, v_w);
    softout_kernel<<<dim3(QQ / TQO, BB, DD / 128), 128>>>(value, valid_len, out);
}